// round 1
// baseline (speedup 1.0000x reference)
#include <cuda_runtime.h>
#include <math.h>

#define D_MODEL 1024
#define D_INNER 2048
#define D_STATE 16
#define DT_RANK 64
#define BATCH   2
#define SEQLEN  2048
#define BL      (BATCH * SEQLEN)   // 4096 rows

// ---------------- scratch (static device globals; no allocation allowed) ---
__device__ float g_xz[(size_t)BL * 2 * D_INNER];   // 64 MB  xz = hs @ W_in (interleaved)
__device__ float g_x[(size_t)BL * D_INNER];        // 32 MB  x after conv+silu
__device__ float g_zs[(size_t)BL * D_INNER];       // 32 MB  silu(z)
__device__ float g_xdbl[(size_t)BL * 96];          // 1.5 MB x_dbl = x @ W_x
__device__ float g_delta[(size_t)BL * D_INNER];    // 32 MB  softplus(dt)
__device__ float g_outpre[(size_t)BL * D_INNER];   // 32 MB  (y + x*D)*silu(z)

__device__ __forceinline__ float ex2f(float x) {
    float y;
    asm("ex2.approx.f32 %0, %1;" : "=f"(y) : "f"(x));
    return y;
}

// ---------------- tiled SGEMM: C[M,N] = A[M,K] @ B[K,N] (+ epilogue) --------
// 128x128 tile, BK=8, 256 threads, 8x8 per thread.
// Requirements used here: M % 128 == 0, K % 8 == 0, N % 4 == 0, lda/ldb % 4 == 0.
// EPI: 0 = plain store, 1 = softplus(acc + bias[col]) store.
template <int EPI>
__global__ __launch_bounds__(256) void sgemm128(
    const float* __restrict__ A, const float* __restrict__ B,
    float* __restrict__ C, const float* __restrict__ bias,
    int M, int N, int K, int lda, int ldb, int ldc)
{
    __shared__ __align__(16) float As[8][128];
    __shared__ __align__(16) float Bs[8][128];

    const int tid  = threadIdx.x;
    const int brow = blockIdx.y * 128;
    const int bcol = blockIdx.x * 128;

    const int arow   = tid >> 1;          // 0..127
    const int acol   = (tid & 1) * 4;     // 0 or 4
    const int brow_k = tid >> 5;          // 0..7
    const int bcol_t = (tid & 31) * 4;    // 0..124

    const int ty = tid >> 4;              // 0..15 -> rows ty*8..
    const int tx = tid & 15;              // 0..15 -> cols tx*8..

    float acc[8][8];
#pragma unroll
    for (int i = 0; i < 8; ++i)
#pragma unroll
        for (int j = 0; j < 8; ++j) acc[i][j] = 0.f;

    const float* Aptr = A + (size_t)(brow + arow) * lda + acol;
    const float* Bptr = B + (size_t)brow_k * ldb + bcol + bcol_t;
    const bool bc_ok = (bcol + bcol_t) < N;

    for (int kt = 0; kt < K; kt += 8) {
        float4 av = *(const float4*)(Aptr + kt);
        As[acol + 0][arow] = av.x;
        As[acol + 1][arow] = av.y;
        As[acol + 2][arow] = av.z;
        As[acol + 3][arow] = av.w;

        float4 bv = make_float4(0.f, 0.f, 0.f, 0.f);
        if (bc_ok) bv = *(const float4*)(Bptr + (size_t)kt * ldb);
        *(float4*)&Bs[brow_k][bcol_t] = bv;

        __syncthreads();
#pragma unroll
        for (int k = 0; k < 8; ++k) {
            float4 a0 = *(const float4*)&As[k][ty * 8];
            float4 a1 = *(const float4*)&As[k][ty * 8 + 4];
            float4 b0 = *(const float4*)&Bs[k][tx * 8];
            float4 b1 = *(const float4*)&Bs[k][tx * 8 + 4];
            float ar[8] = {a0.x, a0.y, a0.z, a0.w, a1.x, a1.y, a1.z, a1.w};
            float br[8] = {b0.x, b0.y, b0.z, b0.w, b1.x, b1.y, b1.z, b1.w};
#pragma unroll
            for (int i = 0; i < 8; ++i)
#pragma unroll
                for (int j = 0; j < 8; ++j)
                    acc[i][j] = fmaf(ar[i], br[j], acc[i][j]);
        }
        __syncthreads();
    }

#pragma unroll
    for (int i = 0; i < 8; ++i) {
        const int row = brow + ty * 8 + i;
#pragma unroll
        for (int jj = 0; jj < 8; jj += 4) {
            const int col = bcol + tx * 8 + jj;
            if (col < N) {
                float v[4];
#pragma unroll
                for (int q = 0; q < 4; ++q) {
                    float t = acc[i][jj + q];
                    if (EPI == 1) {
                        t += bias[col + q];
                        t = (t > 20.f) ? t : log1pf(__expf(t));
                    }
                    v[q] = t;
                }
                *(float4*)&C[(size_t)row * ldc + col] =
                    make_float4(v[0], v[1], v[2], v[3]);
            }
        }
    }
}

// ---------------- depthwise conv (SAME, k=4) + SiLU, + silu(z) --------------
// xz[b,t,2c] -> x stream, xz[b,t,2c+1] -> z stream.
// SAME pad for k=4: taps at t-1, t, t+1, t+2.
__global__ __launch_bounds__(256) void conv_silu_kernel(
    const float* __restrict__ ck, const float* __restrict__ cb)
{
    const int idx = blockIdx.x * blockDim.x + threadIdx.x;  // over BL*D_INNER
    const int c = idx & (D_INNER - 1);
    const int t = (idx >> 11) & (SEQLEN - 1);
    const int b = idx >> 22;

    const float* base = g_xz + (size_t)b * SEQLEN * (2 * D_INNER) + 2 * c;

    float sum = cb[c];
#pragma unroll
    for (int j = 0; j < 4; ++j) {
        const int tt = t - 1 + j;
        if (tt >= 0 && tt < SEQLEN)
            sum = fmaf(base[(size_t)tt * (2 * D_INNER)], ck[j * D_INNER + c], sum);
    }
    const float xv = sum / (1.f + __expf(-sum));
    g_x[idx] = xv;

    const float z = base[(size_t)t * (2 * D_INNER) + 1];
    g_zs[idx] = z / (1.f + __expf(-z));
}

// ---------------- skinny GEMM: x_dbl[BL,96] = g_x[BL,2048] @ W_x[2048,96] ---
// block = 96 threads (one column each) x 16 rows; A chunk staged via SMEM.
__global__ __launch_bounds__(96) void gemm_xdbl(const float* __restrict__ Wx)
{
    __shared__ __align__(16) float As[96][16];   // [k-within-chunk][row]
    const int tid = threadIdx.x;                 // column n, 0..95
    const int m0  = blockIdx.x * 16;

    float acc[16];
#pragma unroll
    for (int i = 0; i < 16; ++i) acc[i] = 0.f;

    for (int k0 = 0; k0 < D_INNER; k0 += 96) {
        const int chunk = min(96, D_INNER - k0);
        // cooperative, coalesced load of A[m0..m0+15, k0..k0+chunk)
#pragma unroll
        for (int i = 0; i < 16; ++i) {
            float v = 0.f;
            if (tid < chunk) v = g_x[(size_t)(m0 + i) * D_INNER + k0 + tid];
            As[tid][i] = v;
        }
        __syncthreads();
        for (int k = 0; k < chunk; ++k) {
            const float bv = __ldg(&Wx[(size_t)(k0 + k) * 96 + tid]);
            const float4* ap = (const float4*)&As[k][0];
#pragma unroll
            for (int q = 0; q < 4; ++q) {
                float4 a = ap[q];
                acc[4 * q + 0] = fmaf(a.x, bv, acc[4 * q + 0]);
                acc[4 * q + 1] = fmaf(a.y, bv, acc[4 * q + 1]);
                acc[4 * q + 2] = fmaf(a.z, bv, acc[4 * q + 2]);
                acc[4 * q + 3] = fmaf(a.w, bv, acc[4 * q + 3]);
            }
        }
        __syncthreads();
    }
#pragma unroll
    for (int i = 0; i < 16; ++i)
        g_xdbl[(size_t)(m0 + i) * 96 + tid] = acc[i];
}

// ---------------- selective scan ------------------------------------------
// Thread = one (b, d, n). Warp = 2 channels x 16 states (both same b).
// state_{l} = exp(delta*A[d,n]) * state_{l-1} + delta * B[l,n] * x[l,d]
// y[l,d] = sum_n state*C[l,n];  outpre = (y + x*D[d]) * silu(z)
__global__ __launch_bounds__(256) void scan_kernel(
    const float* __restrict__ A_log, const float* __restrict__ Dp)
{
    const int tid  = blockIdx.x * blockDim.x + threadIdx.x;
    const int w    = tid >> 5;
    const int lane = tid & 31;
    const int n    = lane & 15;
    const int c    = 2 * w + (lane >> 4);       // channel = b*D_INNER + d
    const int b    = c >> 11;
    const int d    = c & (D_INNER - 1);

    const float coef = -__expf(A_log[d * D_STATE + n]) * 1.44269504088896f;
    const float Dv   = Dp[d];

    float state = 0.f;
    size_t idx = (size_t)b * SEQLEN * D_INNER + d;
    int r96 = b * SEQLEN * 96;

    for (int l = 0; l < SEQLEN; ++l) {
        const float delta = g_delta[idx];
        const float xv    = g_x[idx];
        const float Bv    = g_xdbl[r96 + DT_RANK + n];
        const float Cv    = g_xdbl[r96 + DT_RANK + D_STATE + n];

        const float a = ex2f(delta * coef);
        state = fmaf(a, state, delta * Bv * xv);

        float p = state * Cv;
        p += __shfl_xor_sync(0xffffffffu, p, 8);
        p += __shfl_xor_sync(0xffffffffu, p, 4);
        p += __shfl_xor_sync(0xffffffffu, p, 2);
        p += __shfl_xor_sync(0xffffffffu, p, 1);

        if (n == 0) g_outpre[idx] = (p + xv * Dv) * g_zs[idx];

        idx += D_INNER;
        r96 += 96;
    }
}

// ---------------- launch ----------------------------------------------------
extern "C" void kernel_launch(void* const* d_in, const int* in_sizes, int n_in,
                              void* d_out, int out_size)
{
    const float* hs    = (const float*)d_in[0];
    const float* W_in  = (const float*)d_in[1];
    const float* ck    = (const float*)d_in[2];
    const float* cb    = (const float*)d_in[3];
    const float* W_x   = (const float*)d_in[4];
    const float* W_dt  = (const float*)d_in[5];
    const float* b_dt  = (const float*)d_in[6];
    const float* A_log = (const float*)d_in[7];
    const float* Dp    = (const float*)d_in[8];
    const float* W_out = (const float*)d_in[9];
    float* out = (float*)d_out;

    float *xz, *xdbl, *delta, *outpre;
    cudaGetSymbolAddress((void**)&xz,     g_xz);
    cudaGetSymbolAddress((void**)&xdbl,   g_xdbl);
    cudaGetSymbolAddress((void**)&delta,  g_delta);
    cudaGetSymbolAddress((void**)&outpre, g_outpre);

    // 1) xz = hs @ W_in              (4096x4096x1024)
    sgemm128<0><<<dim3(2 * D_INNER / 128, BL / 128), 256>>>(
        hs, W_in, xz, nullptr, BL, 2 * D_INNER, D_MODEL, D_MODEL, 2 * D_INNER, 2 * D_INNER);

    // 2) conv + silu (x), silu(z)
    conv_silu_kernel<<<(BL * D_INNER) / 256, 256>>>(ck, cb);

    // 3) x_dbl = x @ W_x             (4096x96x2048)
    gemm_xdbl<<<BL / 16, 96>>>(W_x);

    // 4) delta = softplus(x_dbl[:, :64] @ W_dt + b_dt)   (4096x2048x64)
    sgemm128<1><<<dim3(D_INNER / 128, BL / 128), 256>>>(
        xdbl, W_dt, delta, b_dt, BL, D_INNER, DT_RANK, 96, D_INNER, D_INNER);

    // 5) selective scan + gating -> outpre
    scan_kernel<<<(BATCH * D_INNER * D_STATE) / 256, 256>>>(A_log, Dp);

    // 6) out = outpre @ W_out        (4096x1024x2048)
    sgemm128<0><<<dim3(D_MODEL / 128, BL / 128), 256>>>(
        outpre, W_out, out, nullptr, BL, D_MODEL, D_INNER, D_INNER, D_MODEL, D_MODEL);
}

// round 2
// speedup vs baseline: 1.4468x; 1.4468x over previous
#include <cuda_runtime.h>
#include <math.h>

#define D_MODEL 1024
#define D_INNER 2048
#define D_STATE 16
#define DT_RANK 64
#define BATCH   2
#define SEQLEN  2048
#define BL      (BATCH * SEQLEN)   // 4096 rows

// ---------------- scratch (static device globals; no allocation allowed) ---
__device__ float g_xz[(size_t)BL * 2 * D_INNER];   // 64 MB  xz = hs @ W_in (interleaved)
__device__ float g_x[(size_t)BL * D_INNER];        // 32 MB  x after conv+silu
__device__ float g_zs[(size_t)BL * D_INNER];       // 32 MB  silu(z)
__device__ float g_xdbl[(size_t)BL * 96];          // 1.5 MB x_dbl = x @ W_x
__device__ float g_delta[(size_t)BL * D_INNER];    // 32 MB  softplus(dt)
__device__ float g_outpre[(size_t)BL * D_INNER];   // 32 MB  (y + x*D)*silu(z)

__device__ __forceinline__ float ex2f(float x) {
    float y;
    asm("ex2.approx.f32 %0, %1;" : "=f"(y) : "f"(x));
    return y;
}

__device__ __forceinline__ unsigned f2tf(float x) {
    unsigned r;
    asm("cvt.rna.tf32.f32 %0, %1;" : "=r"(r) : "f"(x));
    return r;
}

// ---------------- TF32 tensor-core GEMM -------------------------------------
// C[M,N] = A[M,K] @ B[K,N]  (row-major, fp32 in/out, tf32 mma accumulation)
// 128x128 tile, BK=16, 256 threads (8 warps as 2x4), warp tile 64x32 via
// m16n8k8 tf32 mma. Double-buffered SMEM, LDG->compute->STS pipeline.
// Requires: M%128==0, N%128==0, K%16==0, lda/ldb/ldc %4==0.
// EPI: 0 = plain store, 1 = softplus(acc + bias[col]).
template <int EPI>
__global__ __launch_bounds__(256) void mma_gemm(
    const float* __restrict__ A, const float* __restrict__ B,
    float* __restrict__ C, const float* __restrict__ bias,
    int M, int N, int K, int lda, int ldb, int ldc)
{
    constexpr int BM = 128, BN = 128, BK = 16;
    constexpr int ASTR = BK + 4;   // 20: A frag LDS conflict-free
    constexpr int BSTR = BN + 4;   // 132: B frag LDS conflict-free

    __shared__ unsigned As[2][BM * ASTR];   // [m][k], m-major
    __shared__ unsigned Bs[2][BK * BSTR];   // [k][n]

    const int tid  = threadIdx.x;
    const int warp = tid >> 5;
    const int lane = tid & 31;
    const int brow = blockIdx.y * BM;
    const int bcol = blockIdx.x * BN;

    const int wm = (warp >> 2) * 64;   // warp m offset in tile
    const int wn = (warp & 3) * 32;    // warp n offset in tile

    // global load mapping
    const int a_r = tid >> 2;             // 0..63 (2 passes of 64 rows)
    const int a_c = (tid & 3) * 4;        // 0,4,8,12
    const int b_r = tid >> 5;             // 0..7 (2 passes of 8 rows)
    const int b_c = (lane) * 4;           // 0..124

    const float* Ag = A + (size_t)(brow + a_r) * lda + a_c;
    const float* Bg = B + (size_t)b_r * ldb + bcol + b_c;

    float acc[4][4][4];
#pragma unroll
    for (int i = 0; i < 4; ++i)
#pragma unroll
        for (int j = 0; j < 4; ++j)
#pragma unroll
            for (int q = 0; q < 4; ++q) acc[i][j][q] = 0.f;

    const int ntiles = K / BK;

    // prologue: load tile 0 into buffer 0
    {
        float4 ra0 = *(const float4*)(Ag);
        float4 ra1 = *(const float4*)(Ag + (size_t)64 * lda);
        float4 rb0 = *(const float4*)(Bg);
        float4 rb1 = *(const float4*)(Bg + (size_t)8 * ldb);
        unsigned* as = As[0];
        unsigned* bs = Bs[0];
        as[(a_r)      * ASTR + a_c + 0] = f2tf(ra0.x);
        as[(a_r)      * ASTR + a_c + 1] = f2tf(ra0.y);
        as[(a_r)      * ASTR + a_c + 2] = f2tf(ra0.z);
        as[(a_r)      * ASTR + a_c + 3] = f2tf(ra0.w);
        as[(a_r + 64) * ASTR + a_c + 0] = f2tf(ra1.x);
        as[(a_r + 64) * ASTR + a_c + 1] = f2tf(ra1.y);
        as[(a_r + 64) * ASTR + a_c + 2] = f2tf(ra1.z);
        as[(a_r + 64) * ASTR + a_c + 3] = f2tf(ra1.w);
        bs[(b_r)     * BSTR + b_c + 0] = f2tf(rb0.x);
        bs[(b_r)     * BSTR + b_c + 1] = f2tf(rb0.y);
        bs[(b_r)     * BSTR + b_c + 2] = f2tf(rb0.z);
        bs[(b_r)     * BSTR + b_c + 3] = f2tf(rb0.w);
        bs[(b_r + 8) * BSTR + b_c + 0] = f2tf(rb1.x);
        bs[(b_r + 8) * BSTR + b_c + 1] = f2tf(rb1.y);
        bs[(b_r + 8) * BSTR + b_c + 2] = f2tf(rb1.z);
        bs[(b_r + 8) * BSTR + b_c + 3] = f2tf(rb1.w);
    }
    __syncthreads();

    for (int kt = 0; kt < ntiles; ++kt) {
        const int cur = kt & 1;
        const int nxt = cur ^ 1;

        // issue next tile's global loads early
        float4 ra0, ra1, rb0, rb1;
        const bool more = (kt + 1) < ntiles;
        if (more) {
            const float* Ak = Ag + (size_t)(kt + 1) * BK;
            const float* Bk = Bg + (size_t)(kt + 1) * BK * ldb;
            ra0 = *(const float4*)(Ak);
            ra1 = *(const float4*)(Ak + (size_t)64 * lda);
            rb0 = *(const float4*)(Bk);
            rb1 = *(const float4*)(Bk + (size_t)8 * ldb);
        }

        // compute on current buffer: 2 k-steps of 8
        const unsigned* as = As[cur];
        const unsigned* bs = Bs[cur];
#pragma unroll
        for (int ks = 0; ks < 2; ++ks) {
            const int k8 = ks * 8;
            unsigned af[4][4];
            unsigned bf[4][2];
#pragma unroll
            for (int i = 0; i < 4; ++i) {
                const int m = wm + i * 16 + (lane >> 2);
                const int kk = k8 + (lane & 3);
                af[i][0] = as[(m)     * ASTR + kk];
                af[i][1] = as[(m + 8) * ASTR + kk];
                af[i][2] = as[(m)     * ASTR + kk + 4];
                af[i][3] = as[(m + 8) * ASTR + kk + 4];
            }
#pragma unroll
            for (int j = 0; j < 4; ++j) {
                const int n = wn + j * 8 + (lane >> 2);
                const int kk = k8 + (lane & 3);
                bf[j][0] = bs[(kk)     * BSTR + n];
                bf[j][1] = bs[(kk + 4) * BSTR + n];
            }
#pragma unroll
            for (int i = 0; i < 4; ++i)
#pragma unroll
                for (int j = 0; j < 4; ++j) {
                    asm volatile(
                        "mma.sync.aligned.m16n8k8.row.col.f32.tf32.tf32.f32 "
                        "{%0,%1,%2,%3}, {%4,%5,%6,%7}, {%8,%9}, {%0,%1,%2,%3};"
                        : "+f"(acc[i][j][0]), "+f"(acc[i][j][1]),
                          "+f"(acc[i][j][2]), "+f"(acc[i][j][3])
                        : "r"(af[i][0]), "r"(af[i][1]), "r"(af[i][2]), "r"(af[i][3]),
                          "r"(bf[j][0]), "r"(bf[j][1]));
                }
        }

        if (more) {
            unsigned* asn = As[nxt];
            unsigned* bsn = Bs[nxt];
            asn[(a_r)      * ASTR + a_c + 0] = f2tf(ra0.x);
            asn[(a_r)      * ASTR + a_c + 1] = f2tf(ra0.y);
            asn[(a_r)      * ASTR + a_c + 2] = f2tf(ra0.z);
            asn[(a_r)      * ASTR + a_c + 3] = f2tf(ra0.w);
            asn[(a_r + 64) * ASTR + a_c + 0] = f2tf(ra1.x);
            asn[(a_r + 64) * ASTR + a_c + 1] = f2tf(ra1.y);
            asn[(a_r + 64) * ASTR + a_c + 2] = f2tf(ra1.z);
            asn[(a_r + 64) * ASTR + a_c + 3] = f2tf(ra1.w);
            bsn[(b_r)     * BSTR + b_c + 0] = f2tf(rb0.x);
            bsn[(b_r)     * BSTR + b_c + 1] = f2tf(rb0.y);
            bsn[(b_r)     * BSTR + b_c + 2] = f2tf(rb0.z);
            bsn[(b_r)     * BSTR + b_c + 3] = f2tf(rb0.w);
            bsn[(b_r + 8) * BSTR + b_c + 0] = f2tf(rb1.x);
            bsn[(b_r + 8) * BSTR + b_c + 1] = f2tf(rb1.y);
            bsn[(b_r + 8) * BSTR + b_c + 2] = f2tf(rb1.z);
            bsn[(b_r + 8) * BSTR + b_c + 3] = f2tf(rb1.w);
        }
        __syncthreads();
    }

    // epilogue: per-frag float2 stores
#pragma unroll
    for (int i = 0; i < 4; ++i) {
        const int row0 = brow + wm + i * 16 + (lane >> 2);
#pragma unroll
        for (int j = 0; j < 4; ++j) {
            const int col = bcol + wn + j * 8 + 2 * (lane & 3);
            float v0 = acc[i][j][0], v1 = acc[i][j][1];
            float v2 = acc[i][j][2], v3 = acc[i][j][3];
            if (EPI == 1) {
                const float b0 = bias[col], b1 = bias[col + 1];
                v0 += b0; v1 += b1; v2 += b0; v3 += b1;
                v0 = (v0 > 20.f) ? v0 : log1pf(__expf(v0));
                v1 = (v1 > 20.f) ? v1 : log1pf(__expf(v1));
                v2 = (v2 > 20.f) ? v2 : log1pf(__expf(v2));
                v3 = (v3 > 20.f) ? v3 : log1pf(__expf(v3));
            }
            *(float2*)&C[(size_t)row0 * ldc + col]       = make_float2(v0, v1);
            *(float2*)&C[(size_t)(row0 + 8) * ldc + col] = make_float2(v2, v3);
        }
    }
}

// ---------------- depthwise conv (SAME, k=4) + SiLU, + silu(z) --------------
__global__ __launch_bounds__(256) void conv_silu_kernel(
    const float* __restrict__ ck, const float* __restrict__ cb)
{
    const int idx = blockIdx.x * blockDim.x + threadIdx.x;  // over BL*D_INNER
    const int c = idx & (D_INNER - 1);
    const int t = (idx >> 11) & (SEQLEN - 1);
    const int b = idx >> 22;

    const float* base = g_xz + (size_t)b * SEQLEN * (2 * D_INNER) + 2 * c;

    float sum = cb[c];
#pragma unroll
    for (int j = 0; j < 4; ++j) {
        const int tt = t - 1 + j;
        if (tt >= 0 && tt < SEQLEN)
            sum = fmaf(base[(size_t)tt * (2 * D_INNER)], ck[j * D_INNER + c], sum);
    }
    const float xv = sum / (1.f + __expf(-sum));
    g_x[idx] = xv;

    const float z = base[(size_t)t * (2 * D_INNER) + 1];
    g_zs[idx] = z / (1.f + __expf(-z));
}

// ---------------- skinny GEMM: x_dbl[BL,96] = g_x[BL,2048] @ W_x[2048,96] ---
__global__ __launch_bounds__(96) void gemm_xdbl(const float* __restrict__ Wx)
{
    __shared__ __align__(16) float As[96][16];
    const int tid = threadIdx.x;                 // column n, 0..95
    const int m0  = blockIdx.x * 16;

    float acc[16];
#pragma unroll
    for (int i = 0; i < 16; ++i) acc[i] = 0.f;

    for (int k0 = 0; k0 < D_INNER; k0 += 96) {
        const int chunk = min(96, D_INNER - k0);
#pragma unroll
        for (int i = 0; i < 16; ++i) {
            float v = 0.f;
            if (tid < chunk) v = g_x[(size_t)(m0 + i) * D_INNER + k0 + tid];
            As[tid][i] = v;
        }
        __syncthreads();
        for (int k = 0; k < chunk; ++k) {
            const float bv = __ldg(&Wx[(size_t)(k0 + k) * 96 + tid]);
            const float4* ap = (const float4*)&As[k][0];
#pragma unroll
            for (int q = 0; q < 4; ++q) {
                float4 a = ap[q];
                acc[4 * q + 0] = fmaf(a.x, bv, acc[4 * q + 0]);
                acc[4 * q + 1] = fmaf(a.y, bv, acc[4 * q + 1]);
                acc[4 * q + 2] = fmaf(a.z, bv, acc[4 * q + 2]);
                acc[4 * q + 3] = fmaf(a.w, bv, acc[4 * q + 3]);
            }
        }
        __syncthreads();
    }
#pragma unroll
    for (int i = 0; i < 16; ++i)
        g_xdbl[(size_t)(m0 + i) * 96 + tid] = acc[i];
}

// ---------------- selective scan ------------------------------------------
__global__ __launch_bounds__(256) void scan_kernel(
    const float* __restrict__ A_log, const float* __restrict__ Dp)
{
    const int tid  = blockIdx.x * blockDim.x + threadIdx.x;
    const int w    = tid >> 5;
    const int lane = tid & 31;
    const int n    = lane & 15;
    const int c    = 2 * w + (lane >> 4);       // channel = b*D_INNER + d
    const int b    = c >> 11;
    const int d    = c & (D_INNER - 1);

    const float coef = -__expf(A_log[d * D_STATE + n]) * 1.44269504088896f;
    const float Dv   = Dp[d];

    float state = 0.f;
    size_t idx = (size_t)b * SEQLEN * D_INNER + d;
    int r96 = b * SEQLEN * 96;

    for (int l = 0; l < SEQLEN; ++l) {
        const float delta = g_delta[idx];
        const float xv    = g_x[idx];
        const float Bv    = g_xdbl[r96 + DT_RANK + n];
        const float Cv    = g_xdbl[r96 + DT_RANK + D_STATE + n];

        const float a = ex2f(delta * coef);
        state = fmaf(a, state, delta * Bv * xv);

        float p = state * Cv;
        p += __shfl_xor_sync(0xffffffffu, p, 8);
        p += __shfl_xor_sync(0xffffffffu, p, 4);
        p += __shfl_xor_sync(0xffffffffu, p, 2);
        p += __shfl_xor_sync(0xffffffffu, p, 1);

        if (n == 0) g_outpre[idx] = (p + xv * Dv) * g_zs[idx];

        idx += D_INNER;
        r96 += 96;
    }
}

// ---------------- launch ----------------------------------------------------
extern "C" void kernel_launch(void* const* d_in, const int* in_sizes, int n_in,
                              void* d_out, int out_size)
{
    const float* hs    = (const float*)d_in[0];
    const float* W_in  = (const float*)d_in[1];
    const float* ck    = (const float*)d_in[2];
    const float* cb    = (const float*)d_in[3];
    const float* W_x   = (const float*)d_in[4];
    const float* W_dt  = (const float*)d_in[5];
    const float* b_dt  = (const float*)d_in[6];
    const float* A_log = (const float*)d_in[7];
    const float* Dp    = (const float*)d_in[8];
    const float* W_out = (const float*)d_in[9];
    float* out = (float*)d_out;

    float *xz, *xdbl, *delta, *outpre;
    cudaGetSymbolAddress((void**)&xz,     g_xz);
    cudaGetSymbolAddress((void**)&xdbl,   g_xdbl);
    cudaGetSymbolAddress((void**)&delta,  g_delta);
    cudaGetSymbolAddress((void**)&outpre, g_outpre);

    // 1) xz = hs @ W_in              (4096x4096x1024) tf32 tensor cores
    mma_gemm<0><<<dim3(2 * D_INNER / 128, BL / 128), 256>>>(
        hs, W_in, xz, nullptr, BL, 2 * D_INNER, D_MODEL, D_MODEL, 2 * D_INNER, 2 * D_INNER);

    // 2) conv + silu (x), silu(z)
    conv_silu_kernel<<<(BL * D_INNER) / 256, 256>>>(ck, cb);

    // 3) x_dbl = x @ W_x             (4096x96x2048)
    gemm_xdbl<<<BL / 16, 96>>>(W_x);

    // 4) delta = softplus(x_dbl[:, :64] @ W_dt + b_dt)   (4096x2048x64)
    mma_gemm<1><<<dim3(D_INNER / 128, BL / 128), 256>>>(
        xdbl, W_dt, delta, b_dt, BL, D_INNER, DT_RANK, 96, D_INNER, D_INNER);

    // 5) selective scan + gating -> outpre
    scan_kernel<<<(BATCH * D_INNER * D_STATE) / 256, 256>>>(A_log, Dp);

    // 6) out = outpre @ W_out        (4096x1024x2048) tf32 tensor cores
    mma_gemm<0><<<dim3(D_MODEL / 128, BL / 128), 256>>>(
        outpre, W_out, out, nullptr, BL, D_MODEL, D_INNER, D_INNER, D_MODEL, D_MODEL);
}